// round 16
// baseline (speedup 1.0000x reference)
#include <cuda_runtime.h>
#include <cuda_bf16.h>
#include <math.h>
#include <stdint.h>

// ---------------- problem constants ----------------
#define BB      4
#define SS      2048
#define HIDDEN  1024
#define HEADS   16
#define DH      64
#define LAYERS  4
#define IN_DIM  512
#define OUT_DIM 1024
#define FF_DIM  4096
#define M_ROWS  (BB * SS)          // 8192

// ---------------- scratch (no allocation allowed) ----------------
__device__ float g_h  [(size_t)M_ROWS * HIDDEN];
__device__ float g_qkv[(size_t)M_ROWS * 3 * HIDDEN];
__device__ float g_y  [(size_t)M_ROWS * HIDDEN];

// pre-split weight arenas (hi/lo), stored TRANSPOSED: each matrix is [N][K]
#define W_TOTAL 51904512
__device__ float g_wh[(size_t)W_TOTAL];
__device__ float g_wl[(size_t)W_TOTAL];
// split activation buffers
__device__ float g_ah[(size_t)M_ROWS * HIDDEN];   // h / ctx splits
__device__ float g_al[(size_t)M_ROWS * HIDDEN];
__device__ float g_fh[(size_t)M_ROWS * FF_DIM];   // x split, ff split
__device__ float g_fl[(size_t)M_ROWS * FF_DIM];

// ---------------- tf32 helpers ----------------
__device__ __forceinline__ float tf32r(float x) {
    uint32_t u;
    asm("cvt.rna.tf32.f32 %0, %1;" : "=r"(u) : "f"(x));
    return __uint_as_float(u);
}
__device__ __forceinline__ void split4(float4 v, float4& hi, float4& lo) {
    hi.x = tf32r(v.x); lo.x = tf32r(v.x - hi.x);
    hi.y = tf32r(v.y); lo.y = tf32r(v.y - hi.y);
    hi.z = tf32r(v.z); lo.z = tf32r(v.z - hi.z);
    hi.w = tf32r(v.w); lo.w = tf32r(v.w - hi.w);
}
// D = A(16x8,row) * B(8x8,col) + D, tf32 inputs, f32 accum (float regs)
__device__ __forceinline__ void mma_tf32(float* c, const float* a, const float* b) {
    asm volatile(
        "mma.sync.aligned.m16n8k8.row.col.f32.tf32.tf32.f32 "
        "{%0,%1,%2,%3}, {%4,%5,%6,%7}, {%8,%9}, {%0,%1,%2,%3};\n"
        : "+f"(c[0]), "+f"(c[1]), "+f"(c[2]), "+f"(c[3])
        : "r"(__float_as_uint(a[0])), "r"(__float_as_uint(a[1])),
          "r"(__float_as_uint(a[2])), "r"(__float_as_uint(a[3])),
          "r"(__float_as_uint(b[0])), "r"(__float_as_uint(b[1])));
}
// uint-fragment variant (for ldmatrix-loaded fragments)
__device__ __forceinline__ void mma_tf32u(float* c, const uint32_t* a, const uint32_t* b) {
    asm volatile(
        "mma.sync.aligned.m16n8k8.row.col.f32.tf32.tf32.f32 "
        "{%0,%1,%2,%3}, {%4,%5,%6,%7}, {%8,%9}, {%0,%1,%2,%3};\n"
        : "+f"(c[0]), "+f"(c[1]), "+f"(c[2]), "+f"(c[3])
        : "r"(a[0]), "r"(a[1]), "r"(a[2]), "r"(a[3]),
          "r"(b[0]), "r"(b[1]));
}
// 3xTF32 serial (used by attention, unchanged)
__device__ __forceinline__ void mma3(float* c, const float* ah, const float* al,
                                     const float* bh, const float* bl) {
    mma_tf32(c, ah, bl);
    mma_tf32(c, al, bh);
    mma_tf32(c, ah, bh);
}

__device__ __forceinline__ uint32_t smem_u32(const void* p) {
    uint32_t a;
    asm("{ .reg .u64 t; cvta.to.shared.u64 t, %1; cvt.u32.u64 %0, t; }"
        : "=r"(a) : "l"(p));
    return a;
}
#define CP16(dst_u32, src_ptr) \
    asm volatile("cp.async.cg.shared.global [%0], [%1], 16;" :: "r"(dst_u32), "l"(src_ptr))
#define CP_COMMIT()  asm volatile("cp.async.commit_group;")
#define CP_WAIT0()   asm volatile("cp.async.wait_group 0;")

#define LDSM4(r, addr) \
    asm volatile("ldmatrix.sync.aligned.m8n8.x4.shared.b16 {%0,%1,%2,%3}, [%4];" \
        : "=r"((r)[0]), "=r"((r)[1]), "=r"((r)[2]), "=r"((r)[3]) : "r"(addr))
#define LDSM2(r, addr) \
    asm volatile("ldmatrix.sync.aligned.m8n8.x2.shared.b16 {%0,%1}, [%2];" \
        : "=r"((r)[0]), "=r"((r)[1]) : "r"(addr))

// =================================================================
// One-shot weight split + TRANSPOSE: all 6 weight tensors, original
// layout [K][N], written as [N][K] hi/lo into the arenas.
// Indexed over OUTPUT float4s: coalesced writes, strided reads.
// =================================================================
#define N0_F4 (IN_DIM * HIDDEN / 4)
#define N1_F4 (N0_F4 + LAYERS * HIDDEN * 3 * HIDDEN / 4)
#define N2_F4 (N1_F4 + LAYERS * HIDDEN * HIDDEN / 4)
#define N3_F4 (N2_F4 + LAYERS * HIDDEN * FF_DIM / 4)
#define N4_F4 (N3_F4 + LAYERS * FF_DIM * HIDDEN / 4)
#define N5_F4 (N4_F4 + HIDDEN * OUT_DIM / 4)      // = W_TOTAL/4

__device__ __forceinline__ void wsplit_tr(const float* __restrict__ src,
                                          float* __restrict__ wh,
                                          float* __restrict__ wl,
                                          size_t j, int Ks, int Ns)
{
    const int k4s = Ks / 4;
    const size_t per = (size_t)Ks * Ns / 4;
    int layer = (int)(j / per);
    size_t r = j % per;
    int n  = (int)(r / k4s);
    int k  = (int)(r % k4s) * 4;
    const float* s = src + (size_t)layer * Ks * Ns;
    float4 v;
    v.x = s[(size_t)(k + 0) * Ns + n];
    v.y = s[(size_t)(k + 1) * Ns + n];
    v.z = s[(size_t)(k + 2) * Ns + n];
    v.w = s[(size_t)(k + 3) * Ns + n];
    float4 h, l;
    split4(v, h, l);
    size_t o = ((size_t)layer * Ks * Ns + (size_t)n * Ks + k) / 4;
    ((float4*)wh)[o] = h;
    ((float4*)wl)[o] = l;
}

__global__ void __launch_bounds__(256)
split_weights(const float* __restrict__ s0, const float* __restrict__ s1,
              const float* __restrict__ s2, const float* __restrict__ s3,
              const float* __restrict__ s4, const float* __restrict__ s5,
              float* __restrict__ wh, float* __restrict__ wl)
{
    size_t i = (size_t)blockIdx.x * 256 + threadIdx.x;
    if (i >= (size_t)N5_F4) return;
    if      (i < N0_F4) wsplit_tr(s0, wh,                wl,                i,          IN_DIM, HIDDEN);
    else if (i < N1_F4) wsplit_tr(s1, wh + 4ul*N0_F4,    wl + 4ul*N0_F4,    i - N0_F4,  HIDDEN, 3 * HIDDEN);
    else if (i < N2_F4) wsplit_tr(s2, wh + 4ul*N1_F4,    wl + 4ul*N1_F4,    i - N1_F4,  HIDDEN, HIDDEN);
    else if (i < N3_F4) wsplit_tr(s3, wh + 4ul*N2_F4,    wl + 4ul*N2_F4,    i - N2_F4,  HIDDEN, FF_DIM);
    else if (i < N4_F4) wsplit_tr(s4, wh + 4ul*N3_F4,    wl + 4ul*N3_F4,    i - N3_F4,  FF_DIM, HIDDEN);
    else                wsplit_tr(s5, wh + 4ul*N4_F4,    wl + 4ul*N4_F4,    i - N4_F4,  HIDDEN, OUT_DIM);
}

// =================================================================
// Elementwise hi/lo split (used only for x)
// =================================================================
__global__ void __launch_bounds__(256)
split_kernel(const float* __restrict__ src, float* __restrict__ hi,
             float* __restrict__ lo, int n4)
{
    int i = blockIdx.x * blockDim.x + threadIdx.x;
    if (i < n4) {
        float4 v = ((const float4*)src)[i];
        float4 h, l;
        split4(v, h, l);
        ((float4*)hi)[i] = h;
        ((float4*)lo)[i] = l;
    }
}

// =================================================================
// Tensor-core GEMM (3xTF32), pre-split inputs, cp.async 2-stage,
// ldmatrix fragment loads. B (weights) is [N][K] (transposed).
// EPI: 0 = bias, 1 = bias+relu, 2 = bias then *32 + posenc
// SOUT: 0 = write C fp32; 1 = write Ch/Cl split; 2 = both
// Stage: Ah[128][20], Al[128][20], Bh[128][20], Bl[128][20]
// =================================================================
#define AS_F  (128 * 20)                        // 2560 floats per component
#define STG_F (4 * AS_F)                        // 10240 floats per stage
#define GEMM_SMEM (2 * STG_F * sizeof(float))   // 81920 B -> 2 CTAs/SM

template<int EPI, int SOUT>
__global__ void __launch_bounds__(256, 2)
gemm_tc(const float* __restrict__ Ah, const float* __restrict__ Al,
        const float* __restrict__ Bh, const float* __restrict__ Bl,
        const float* __restrict__ bias, float* __restrict__ C,
        float* __restrict__ Ch, float* __restrict__ Cl,
        int M, int N, int K)
{
    extern __shared__ __align__(16) float smp[];
    const uint32_t sbase = smem_u32(smp);

    const int tid = threadIdx.x;
    const int cb = blockIdx.x * 128;
    const int rb = blockIdx.y * 128;

    // cp.async addressing: 128 rows x 16 k-floats per component, identical A/B
    const int arow = tid >> 1;           // 0..127
    const int ac0  = (tid & 1) * 8;      // 0 or 8

    const float* gAh = Ah + (size_t)(rb + arow) * K + ac0;
    const float* gAl = Al + (size_t)(rb + arow) * K + ac0;
    const float* gBh = Bh + (size_t)(cb + arow) * K + ac0;  // [N][K]
    const float* gBl = Bl + (size_t)(cb + arow) * K + ac0;

    const int wid = tid >> 5, lane = tid & 31;
    const int grp = lane >> 2, t4 = lane & 3;
    const int m0 = (wid >> 2) * 64;
    const int n0 = (wid & 3) * 32;

    // per-thread smem byte offsets within a stage (cp.async writes)
    const uint32_t oA = (uint32_t)(arow * 20 + ac0) * 4;

    auto issue_stage = [&](int s, int k0) {
        uint32_t sb = sbase + (uint32_t)(s * STG_F) * 4;
        const float* p;
        p = gAh + k0; CP16(sb + oA,                 p); CP16(sb + oA + 16,                 p + 4);
        p = gAl + k0; CP16(sb + oA + AS_F * 4,      p); CP16(sb + oA + AS_F * 4 + 16,      p + 4);
        p = gBh + k0; CP16(sb + oA + 2 * AS_F * 4,  p); CP16(sb + oA + 2 * AS_F * 4 + 16,  p + 4);
        p = gBl + k0; CP16(sb + oA + 3 * AS_F * 4,  p); CP16(sb + oA + 3 * AS_F * 4 + 16,  p + 4);
        CP_COMMIT();
    };

    // ldmatrix lane addressing
    const int a_lrow = lane & 15;              // row within m16 group
    const int a_lcol = (lane >> 4) * 4;        // 0 or 4 (tf32 col block)
    const int b_lrow = lane & 7;               // row within n8 group
    const int b_lcol = ((lane >> 3) & 1) * 4;  // 0 or 4 (lanes 0-15 used)

    float acc[4][4][4];
#pragma unroll
    for (int mt = 0; mt < 4; mt++)
#pragma unroll
        for (int nt = 0; nt < 4; nt++)
#pragma unroll
            for (int j = 0; j < 4; j++) acc[mt][nt][j] = 0.f;

    const int ntile = K / 16;
    issue_stage(0, 0);

    for (int i = 0; i < ntile; i++) {
        CP_WAIT0();          // this thread's stage-i loads done
        __syncthreads();     // all threads' loads visible; compute(i-1) done
        if (i + 1 < ntile) issue_stage((i + 1) & 1, (i + 1) * 16);

        const uint32_t stg = sbase + (uint32_t)((i & 1) * STG_F) * 4;

#pragma unroll
        for (int k8i = 0; k8i < 2; k8i++) {
            const int k8 = k8i * 8;
            uint32_t ah[4][4], al[4][4], bh[4][2], bl[4][2];
#pragma unroll
            for (int mt = 0; mt < 4; mt++) {
                uint32_t ao = stg + (uint32_t)((m0 + mt * 16 + a_lrow) * 20 + k8 + a_lcol) * 4;
                LDSM4(ah[mt], ao);
                LDSM4(al[mt], ao + AS_F * 4);
            }
#pragma unroll
            for (int nt = 0; nt < 4; nt++) {
                uint32_t bo = stg + (uint32_t)(2 * AS_F + (n0 + nt * 8 + b_lrow) * 20 + k8 + b_lcol) * 4;
                LDSM2(bh[nt], bo);
                LDSM2(bl[nt], bo + AS_F * 4);
            }
            // three passes, each 16 independent mmas
#pragma unroll
            for (int mt = 0; mt < 4; mt++)
#pragma unroll
                for (int nt = 0; nt < 4; nt++)
                    mma_tf32u(acc[mt][nt], ah[mt], bl[nt]);
#pragma unroll
            for (int mt = 0; mt < 4; mt++)
#pragma unroll
                for (int nt = 0; nt < 4; nt++)
                    mma_tf32u(acc[mt][nt], al[mt], bh[nt]);
#pragma unroll
            for (int mt = 0; mt < 4; mt++)
#pragma unroll
                for (int nt = 0; nt < 4; nt++)
                    mma_tf32u(acc[mt][nt], ah[mt], bh[nt]);
        }
    }

    // ---- epilogue ----
#pragma unroll
    for (int mt = 0; mt < 4; mt++) {
#pragma unroll
        for (int nt = 0; nt < 4; nt++) {
            int col = cb + n0 + nt * 8 + 2 * t4;
            float b0 = bias[col], b1 = bias[col + 1];
#pragma unroll
            for (int half = 0; half < 2; half++) {
                int row = rb + m0 + mt * 16 + grp + half * 8;
                float c0 = acc[mt][nt][half * 2 + 0] + b0;
                float c1 = acc[mt][nt][half * 2 + 1] + b1;
                if (EPI == 1) { c0 = fmaxf(c0, 0.f); c1 = fmaxf(c1, 0.f); }
                if (EPI == 2) {
                    int srow = row & (SS - 1);
                    float f0 = expf(-9.210340371976184f * (float)(col & ~1) * (1.0f / 1024.0f));
                    float f1 = expf(-9.210340371976184f * (float)((col + 1) & ~1) * (1.0f / 1024.0f));
                    float a0 = (float)srow * f0, a1 = (float)srow * f1;
                    float p0 = (col & 1) ? cosf(a0) : sinf(a0);
                    float p1 = ((col + 1) & 1) ? cosf(a1) : sinf(a1);
                    c0 = c0 * 32.0f + p0;
                    c1 = c1 * 32.0f + p1;
                }
                size_t idx = (size_t)row * N + col;
                if (SOUT != 1) {
                    float2 o = {c0, c1};
                    *(float2*)(C + idx) = o;
                }
                if (SOUT >= 1) {
                    float h0 = tf32r(c0), h1 = tf32r(c1);
                    float2 oh = {h0, h1};
                    float2 ol = {tf32r(c0 - h0), tf32r(c1 - h1)};
                    *(float2*)(Ch + idx) = oh;
                    *(float2*)(Cl + idx) = ol;
                }
            }
        }
    }
}

// =================================================================
// Flash attention, 3xTF32 tensor cores, register-prefetched K/V.
// (unchanged from R13 passing version)
// =================================================================
#define ASTR 68
#define ATTN_SMEM ((2 * 128 * ASTR + 2 * 64 * ASTR + 2 * 64 * ASTR + 2 * 128 * ASTR) * sizeof(float))  // 208896

__global__ void __launch_bounds__(256)
attn_tc(const float* __restrict__ qkv, float* __restrict__ ctxh,
        float* __restrict__ ctxl)
{
    extern __shared__ float sm[];
    float* Qh = sm;                  // [128][68]
    float* Ql = Qh + 128 * ASTR;
    float* Kh = Ql + 128 * ASTR;     // [64][68]
    float* Kl = Kh + 64 * ASTR;
    float* Vh = Kl + 64 * ASTR;      // [64][68]
    float* Vl = Vh + 64 * ASTR;
    float* Ph = Vl + 64 * ASTR;      // [128][68]
    float* Pl = Ph + 128 * ASTR;

    const int tid = threadIdx.x;
    const int q0 = blockIdx.x * 128;
    const int h  = blockIdx.y;
    const int b  = blockIdx.z;

    const int wid = tid >> 5, lane = tid & 31;
    const int grp = lane >> 2, t4 = lane & 3;
    const int mw = wid * 16;

    const int kv_r = tid >> 4;
    const int kv_c = (tid & 15) * 4;

    // ---- load Q tile (128 x 64), hi/lo split ----
    {
        const float* qbase = qkv + (size_t)(b * SS + q0) * 3 * HIDDEN + h * DH;
#pragma unroll
        for (int u = 0; u < 8; u++) {
            int idx = tid + u * 256;
            int r = idx >> 4, c = (idx & 15) * 4;
            float4 v = *(const float4*)(qbase + (size_t)r * 3 * HIDDEN + c);
            float4 hi, lo;
            split4(v, hi, lo);
            *(float4*)&Qh[r * ASTR + c] = hi;
            *(float4*)&Ql[r * ASTR + c] = lo;
        }
    }

    float out[8][4];
    float mi0 = -1e30f, mi1 = -1e30f, li0 = 0.f, li1 = 0.f;
#pragma unroll
    for (int nt = 0; nt < 8; nt++)
#pragma unroll
        for (int j = 0; j < 4; j++) out[nt][j] = 0.f;

    float4 kvr[4], vvr[4];
    {
        const float* kb = qkv + ((size_t)(b * SS) * 3 + 1) * HIDDEN + h * DH;
        const float* vb = kb + HIDDEN;
#pragma unroll
        for (int u = 0; u < 4; u++) {
            int r = kv_r + u * 16;
            kvr[u] = *(const float4*)(kb + (size_t)r * 3 * HIDDEN + kv_c);
            vvr[u] = *(const float4*)(vb + (size_t)r * 3 * HIDDEN + kv_c);
        }
    }

    for (int kt = 0; kt < SS / 64; kt++) {
#pragma unroll
        for (int u = 0; u < 4; u++) {
            int r = kv_r + u * 16;
            float4 hi, lo;
            split4(kvr[u], hi, lo);
            *(float4*)&Kh[r * ASTR + kv_c] = hi;
            *(float4*)&Kl[r * ASTR + kv_c] = lo;
            split4(vvr[u], hi, lo);
            *(float4*)&Vh[r * ASTR + kv_c] = hi;
            *(float4*)&Vl[r * ASTR + kv_c] = lo;
        }
        __syncthreads();

        if (kt + 1 < SS / 64) {
            const float* kb = qkv + ((size_t)(b * SS + (kt + 1) * 64) * 3 + 1) * HIDDEN + h * DH;
            const float* vb = kb + HIDDEN;
#pragma unroll
            for (int u = 0; u < 4; u++) {
                int r = kv_r + u * 16;
                kvr[u] = *(const float4*)(kb + (size_t)r * 3 * HIDDEN + kv_c);
                vvr[u] = *(const float4*)(vb + (size_t)r * 3 * HIDDEN + kv_c);
            }
        }

        // ---- S = Q @ K^T ----
        float sc[8][4];
#pragma unroll
        for (int nt = 0; nt < 8; nt++)
#pragma unroll
            for (int j = 0; j < 4; j++) sc[nt][j] = 0.f;

#pragma unroll
        for (int k8 = 0; k8 < 64; k8 += 8) {
            float ah[4], al[4];
            int mr = mw + grp;
            ah[0] = Qh[mr * ASTR + k8 + t4];
            ah[1] = Qh[(mr + 8) * ASTR + k8 + t4];
            ah[2] = Qh[mr * ASTR + k8 + t4 + 4];
            ah[3] = Qh[(mr + 8) * ASTR + k8 + t4 + 4];
            al[0] = Ql[mr * ASTR + k8 + t4];
            al[1] = Ql[(mr + 8) * ASTR + k8 + t4];
            al[2] = Ql[mr * ASTR + k8 + t4 + 4];
            al[3] = Ql[(mr + 8) * ASTR + k8 + t4 + 4];
#pragma unroll
            for (int nt = 0; nt < 8; nt++) {
                float bh[2], bl[2];
                int kr = nt * 8 + grp;
                bh[0] = Kh[kr * ASTR + k8 + t4];
                bh[1] = Kh[kr * ASTR + k8 + t4 + 4];
                bl[0] = Kl[kr * ASTR + k8 + t4];
                bl[1] = Kl[kr * ASTR + k8 + t4 + 4];
                mma3(sc[nt], ah, al, bh, bl);
            }
        }

        // ---- online softmax ----
        float rm0 = -1e30f, rm1 = -1e30f;
#pragma unroll
        for (int nt = 0; nt < 8; nt++) {
#pragma unroll
            for (int j = 0; j < 4; j++) sc[nt][j] *= 0.125f;
            rm0 = fmaxf(rm0, fmaxf(sc[nt][0], sc[nt][1]));
            rm1 = fmaxf(rm1, fmaxf(sc[nt][2], sc[nt][3]));
        }
#pragma unroll
        for (int off = 1; off < 4; off <<= 1) {
            rm0 = fmaxf(rm0, __shfl_xor_sync(0xffffffffu, rm0, off));
            rm1 = fmaxf(rm1, __shfl_xor_sync(0xffffffffu, rm1, off));
        }
        float mn0 = fmaxf(mi0, rm0), mn1 = fmaxf(mi1, rm1);
        float rs0 = 0.f, rs1 = 0.f;
#pragma unroll
        for (int nt = 0; nt < 8; nt++) {
            sc[nt][0] = __expf(sc[nt][0] - mn0);
            sc[nt][1] = __expf(sc[nt][1] - mn0);
            sc[nt][2] = __expf(sc[nt][2] - mn1);
            sc[nt][3] = __expf(sc[nt][3] - mn1);
            rs0 += sc[nt][0] + sc[nt][1];
            rs1 += sc[nt][2] + sc[nt][3];
        }
#pragma unroll
        for (int off = 1; off < 4; off <<= 1) {
            rs0 += __shfl_xor_sync(0xffffffffu, rs0, off);
            rs1 += __shfl_xor_sync(0xffffffffu, rs1, off);
        }
        float al0 = __expf(mi0 - mn0), al1 = __expf(mi1 - mn1);
        li0 = li0 * al0 + rs0;
        li1 = li1 * al1 + rs1;
        mi0 = mn0; mi1 = mn1;

        int pr0 = (mw + grp) * ASTR, pr1 = (mw + grp + 8) * ASTR;
#pragma unroll
        for (int nt = 0; nt < 8; nt++) {
            out[nt][0] *= al0; out[nt][1] *= al0;
            out[nt][2] *= al1; out[nt][3] *= al1;
            int pc = nt * 8 + 2 * t4;
            float h0 = tf32r(sc[nt][0]), h1 = tf32r(sc[nt][1]);
            float h2 = tf32r(sc[nt][2]), h3 = tf32r(sc[nt][3]);
            float2 ph0 = {h0, h1}, ph1 = {h2, h3};
            float2 pl0 = {tf32r(sc[nt][0] - h0), tf32r(sc[nt][1] - h1)};
            float2 pl1 = {tf32r(sc[nt][2] - h2), tf32r(sc[nt][3] - h3)};
            *(float2*)&Ph[pr0 + pc] = ph0;
            *(float2*)&Ph[pr1 + pc] = ph1;
            *(float2*)&Pl[pr0 + pc] = pl0;
            *(float2*)&Pl[pr1 + pc] = pl1;
        }
        __syncwarp();

        // ---- out += P @ V ----
#pragma unroll
        for (int k8 = 0; k8 < 64; k8 += 8) {
            float ah[4], al[4];
            int mr = mw + grp;
            ah[0] = Ph[mr * ASTR + k8 + t4];
            ah[1] = Ph[(mr + 8) * ASTR + k8 + t4];
            ah[2] = Ph[mr * ASTR + k8 + t4 + 4];
            ah[3] = Ph[(mr + 8) * ASTR + k8 + t4 + 4];
            al[0] = Pl[mr * ASTR + k8 + t4];
            al[1] = Pl[(mr + 8) * ASTR + k8 + t4];
            al[2] = Pl[mr * ASTR + k8 + t4 + 4];
            al[3] = Pl[(mr + 8) * ASTR + k8 + t4 + 4];
#pragma unroll
            for (int nt = 0; nt < 8; nt++) {
                float bh[2], bl[2];
                int nc = nt * 8 + grp;
                bh[0] = Vh[(k8 + t4) * ASTR + nc];
                bh[1] = Vh[(k8 + t4 + 4) * ASTR + nc];
                bl[0] = Vl[(k8 + t4) * ASTR + nc];
                bl[1] = Vl[(k8 + t4 + 4) * ASTR + nc];
                mma3(out[nt], ah, al, bh, bl);
            }
        }
        __syncthreads();
    }

    // ---- write ctx pre-split ----
    float inv0 = 1.0f / li0, inv1 = 1.0f / li1;
    size_t row0 = (size_t)(b * SS + q0 + mw + grp) * HIDDEN + h * DH;
    size_t row1 = row0 + (size_t)8 * HIDDEN;
#pragma unroll
    for (int nt = 0; nt < 8; nt++) {
        int col = nt * 8 + 2 * t4;
        float v0 = out[nt][0] * inv0, v1 = out[nt][1] * inv0;
        float v2 = out[nt][2] * inv1, v3 = out[nt][3] * inv1;
        float h0 = tf32r(v0), h1 = tf32r(v1), h2 = tf32r(v2), h3 = tf32r(v3);
        float2 oh0 = {h0, h1}, oh1 = {h2, h3};
        float2 ol0 = {tf32r(v0 - h0), tf32r(v1 - h1)};
        float2 ol1 = {tf32r(v2 - h2), tf32r(v3 - h3)};
        *(float2*)&ctxh[row0 + col] = oh0;
        *(float2*)&ctxl[row0 + col] = ol0;
        *(float2*)&ctxh[row1 + col] = oh1;
        *(float2*)&ctxl[row1 + col] = ol1;
    }
}

// =================================================================
// LayerNorm: out = LN(x + res) * g + b; optional fp32 out and/or
// split (hi/lo) outputs.
// =================================================================
__global__ void __launch_bounds__(256)
ln_kernel(const float* __restrict__ x, const float* __restrict__ res,
          const float* __restrict__ g, const float* __restrict__ beta,
          float* __restrict__ out, float* __restrict__ oh,
          float* __restrict__ ol)
{
    const int row = blockIdx.x;
    const int t = threadIdx.x;

    float4 v = ((const float4*)(x + (size_t)row * HIDDEN))[t];
    if (res) {
        float4 r = ((const float4*)(res + (size_t)row * HIDDEN))[t];
        v.x += r.x; v.y += r.y; v.z += r.z; v.w += r.w;
    }
    float s  = v.x + v.y + v.z + v.w;
    float sq = v.x * v.x + v.y * v.y + v.z * v.z + v.w * v.w;

#pragma unroll
    for (int off = 16; off > 0; off >>= 1) {
        s  += __shfl_xor_sync(0xffffffffu, s,  off);
        sq += __shfl_xor_sync(0xffffffffu, sq, off);
    }
    __shared__ float ss[8], ssq[8];
    __shared__ float smean, srstd;
    int warp = t >> 5, lane = t & 31;
    if (lane == 0) { ss[warp] = s; ssq[warp] = sq; }
    __syncthreads();
    if (t == 0) {
        float S = 0.f, Q = 0.f;
#pragma unroll
        for (int i = 0; i < 8; i++) { S += ss[i]; Q += ssq[i]; }
        float mean = S * (1.0f / HIDDEN);
        float var  = Q * (1.0f / HIDDEN) - mean * mean;
        smean = mean;
        srstd = rsqrtf(var + 1e-5f);
    }
    __syncthreads();
    float mean = smean, rstd = srstd;

    float4 gg = ((const float4*)g)[t];
    float4 bb = ((const float4*)beta)[t];
    float4 o;
    o.x = (v.x - mean) * rstd * gg.x + bb.x;
    o.y = (v.y - mean) * rstd * gg.y + bb.y;
    o.z = (v.z - mean) * rstd * gg.z + bb.z;
    o.w = (v.w - mean) * rstd * gg.w + bb.w;
    if (out) ((float4*)(out + (size_t)row * HIDDEN))[t] = o;
    if (oh) {
        float4 hi, lo;
        split4(o, hi, lo);
        ((float4*)(oh + (size_t)row * HIDDEN))[t] = hi;
        ((float4*)(ol + (size_t)row * HIDDEN))[t] = lo;
    }
}

// =================================================================
// launch
// =================================================================
extern "C" void kernel_launch(void* const* d_in, const int* in_sizes, int n_in,
                              void* d_out, int out_size)
{
    const float* x     = (const float*)d_in[0];
    const float* in_W  = (const float*)d_in[1];
    const float* in_b  = (const float*)d_in[2];
    const float* qkv_W = (const float*)d_in[3];
    const float* qkv_b = (const float*)d_in[4];
    const float* out_W = (const float*)d_in[5];
    const float* out_b = (const float*)d_in[6];
    const float* ln1_g = (const float*)d_in[7];
    const float* ln1_b = (const float*)d_in[8];
    const float* ln2_g = (const float*)d_in[9];
    const float* ln2_b = (const float*)d_in[10];
    const float* ff1_W = (const float*)d_in[11];
    const float* ff1_b = (const float*)d_in[12];
    const float* ff2_W = (const float*)d_in[13];
    const float* ff2_b = (const float*)d_in[14];
    const float* fin_g = (const float*)d_in[15];
    const float* fin_b = (const float*)d_in[16];
    const float* op_W  = (const float*)d_in[17];
    const float* op_b  = (const float*)d_in[18];
    float* out = (float*)d_out;

    float *h, *qkv, *y, *wh, *wl, *ah, *al, *fh, *fl;
    cudaGetSymbolAddress((void**)&h,   g_h);
    cudaGetSymbolAddress((void**)&qkv, g_qkv);
    cudaGetSymbolAddress((void**)&y,   g_y);
    cudaGetSymbolAddress((void**)&wh,  g_wh);
    cudaGetSymbolAddress((void**)&wl,  g_wl);
    cudaGetSymbolAddress((void**)&ah,  g_ah);
    cudaGetSymbolAddress((void**)&al,  g_al);
    cudaGetSymbolAddress((void**)&fh,  g_fh);
    cudaGetSymbolAddress((void**)&fl,  g_fl);

    cudaFuncSetAttribute(attn_tc, cudaFuncAttributeMaxDynamicSharedMemorySize,
                         (int)ATTN_SMEM);
    cudaFuncSetAttribute((gemm_tc<0,0>), cudaFuncAttributeMaxDynamicSharedMemorySize, (int)GEMM_SMEM);
    cudaFuncSetAttribute((gemm_tc<1,1>), cudaFuncAttributeMaxDynamicSharedMemorySize, (int)GEMM_SMEM);
    cudaFuncSetAttribute((gemm_tc<2,2>), cudaFuncAttributeMaxDynamicSharedMemorySize, (int)GEMM_SMEM);

    const int M = M_ROWS;
    dim3 blk(256);

    // weight arena offsets (floats) — each matrix stored [N][K]
    const size_t ofs_in  = 0;
    const size_t ofs_qkv = ofs_in  + (size_t)IN_DIM * HIDDEN;
    const size_t ofs_out = ofs_qkv + (size_t)LAYERS * HIDDEN * 3 * HIDDEN;
    const size_t ofs_ff1 = ofs_out + (size_t)LAYERS * HIDDEN * HIDDEN;
    const size_t ofs_ff2 = ofs_ff1 + (size_t)LAYERS * HIDDEN * FF_DIM;
    const size_t ofs_op  = ofs_ff2 + (size_t)LAYERS * FF_DIM * HIDDEN;

    // L0: all weights split + transposed in one launch
    split_weights<<<(N5_F4 + 255) / 256, blk>>>(in_W, qkv_W, out_W, ff1_W,
                                                ff2_W, op_W, wh, wl);
    // L1: x split (into fh/fl so gemm<2> can write ah/al)
    {
        int n4 = M * IN_DIM / 4;
        split_kernel<<<(n4 + 255) / 256, blk>>>(x, fh, fl, n4);
    }
    // L2: input projection + posenc; writes h fp32 AND h split
    gemm_tc<2, 2><<<dim3(HIDDEN / 128, M / 128), blk, GEMM_SMEM>>>(
        fh, fl, wh + ofs_in, wl + ofs_in, in_b, h, ah, al, M, HIDDEN, IN_DIM);

    for (int l = 0; l < LAYERS; l++) {
        const float* qb  = qkv_b + (size_t)l * 3 * HIDDEN;
        const float* ob  = out_b + (size_t)l * HIDDEN;
        const float* f1b = ff1_b + (size_t)l * FF_DIM;
        const float* f2b = ff2_b + (size_t)l * HIDDEN;
        size_t wq  = ofs_qkv + (size_t)l * HIDDEN * 3 * HIDDEN;
        size_t wo  = ofs_out + (size_t)l * HIDDEN * HIDDEN;
        size_t wf1 = ofs_ff1 + (size_t)l * HIDDEN * FF_DIM;
        size_t wf2 = ofs_ff2 + (size_t)l * FF_DIM * HIDDEN;

        // qkv projection (reads h split)
        gemm_tc<0, 0><<<dim3(3 * HIDDEN / 128, M / 128), blk, GEMM_SMEM>>>(
            ah, al, wh + wq, wl + wq, qb, qkv, nullptr, nullptr, M, 3 * HIDDEN, HIDDEN);
        // attention: writes ctx split into ah/al (qkv gemm has consumed them)
        attn_tc<<<dim3(SS / 128, HEADS, BB), blk, ATTN_SMEM>>>(qkv, ah, al);
        // out projection (reads ctx split)
        gemm_tc<0, 0><<<dim3(HIDDEN / 128, M / 128), blk, GEMM_SMEM>>>(
            ah, al, wh + wo, wl + wo, ob, y, nullptr, nullptr, M, HIDDEN, HIDDEN);
        // LN1: h = LN(h + y); writes fp32 h + h split
        ln_kernel<<<M, blk>>>(h, y, ln1_g + l * HIDDEN, ln1_b + l * HIDDEN, h, ah, al);
        // FF1 (reads h split), relu, writes ff split
        gemm_tc<1, 1><<<dim3(FF_DIM / 128, M / 128), blk, GEMM_SMEM>>>(
            ah, al, wh + wf1, wl + wf1, f1b, nullptr, fh, fl, M, FF_DIM, HIDDEN);
        // FF2 (reads ff split)
        gemm_tc<0, 0><<<dim3(HIDDEN / 128, M / 128), blk, GEMM_SMEM>>>(
            fh, fl, wh + wf2, wl + wf2, f2b, y, nullptr, nullptr, M, HIDDEN, FF_DIM);
        // LN2: h = LN(h + y); writes fp32 h + h split (for next layer's qkv)
        ln_kernel<<<M, blk>>>(h, y, ln2_g + l * HIDDEN, ln2_b + l * HIDDEN, h, ah, al);
    }

    // final LN (split only) then output projection
    ln_kernel<<<M, blk>>>(h, nullptr, fin_g, fin_b, nullptr, ah, al);
    gemm_tc<0, 0><<<dim3(OUT_DIM / 128, M / 128), blk, GEMM_SMEM>>>(
        ah, al, wh + ofs_op, wl + ofs_op, op_b, out, nullptr, nullptr, M, OUT_DIM, HIDDEN);
}

// round 17
// speedup vs baseline: 1.4879x; 1.4879x over previous
#include <cuda_runtime.h>
#include <cuda_bf16.h>
#include <math.h>
#include <stdint.h>

// ---------------- problem constants ----------------
#define BB      4
#define SS      2048
#define HIDDEN  1024
#define HEADS   16
#define DH      64
#define LAYERS  4
#define IN_DIM  512
#define OUT_DIM 1024
#define FF_DIM  4096
#define M_ROWS  (BB * SS)          // 8192

// ---------------- scratch (no allocation allowed) ----------------
__device__ float g_h  [(size_t)M_ROWS * HIDDEN];
__device__ float g_qkv[(size_t)M_ROWS * 3 * HIDDEN];
__device__ float g_y  [(size_t)M_ROWS * HIDDEN];

// bf16 hi/lo weight arenas, TRANSPOSED: each matrix stored [N][K]
#define W_TOTAL 51904512
__device__ __nv_bfloat16 g_wh[(size_t)W_TOTAL];
__device__ __nv_bfloat16 g_wl[(size_t)W_TOTAL];
// bf16 hi/lo activation buffers
__device__ __nv_bfloat16 g_ah[(size_t)M_ROWS * HIDDEN];   // h / ctx splits
__device__ __nv_bfloat16 g_al[(size_t)M_ROWS * HIDDEN];
__device__ __nv_bfloat16 g_fh[(size_t)M_ROWS * FF_DIM];   // x split, ff split
__device__ __nv_bfloat16 g_fl[(size_t)M_ROWS * FF_DIM];

// ---------------- tf32 helpers (attention only) ----------------
__device__ __forceinline__ float tf32r(float x) {
    uint32_t u;
    asm("cvt.rna.tf32.f32 %0, %1;" : "=r"(u) : "f"(x));
    return __uint_as_float(u);
}
__device__ __forceinline__ void split4(float4 v, float4& hi, float4& lo) {
    hi.x = tf32r(v.x); lo.x = tf32r(v.x - hi.x);
    hi.y = tf32r(v.y); lo.y = tf32r(v.y - hi.y);
    hi.z = tf32r(v.z); lo.z = tf32r(v.z - hi.z);
    hi.w = tf32r(v.w); lo.w = tf32r(v.w - hi.w);
}
__device__ __forceinline__ void mma_tf32(float* c, const float* a, const float* b) {
    asm volatile(
        "mma.sync.aligned.m16n8k8.row.col.f32.tf32.tf32.f32 "
        "{%0,%1,%2,%3}, {%4,%5,%6,%7}, {%8,%9}, {%0,%1,%2,%3};\n"
        : "+f"(c[0]), "+f"(c[1]), "+f"(c[2]), "+f"(c[3])
        : "r"(__float_as_uint(a[0])), "r"(__float_as_uint(a[1])),
          "r"(__float_as_uint(a[2])), "r"(__float_as_uint(a[3])),
          "r"(__float_as_uint(b[0])), "r"(__float_as_uint(b[1])));
}
__device__ __forceinline__ void mma3(float* c, const float* ah, const float* al,
                                     const float* bh, const float* bl) {
    mma_tf32(c, ah, bl);
    mma_tf32(c, al, bh);
    mma_tf32(c, ah, bh);
}

// ---------------- bf16 helpers ----------------
__device__ __forceinline__ uint32_t pk(__nv_bfloat16 a, __nv_bfloat16 b) {
    __nv_bfloat162 t; t.x = a; t.y = b;
    return *reinterpret_cast<uint32_t*>(&t);
}
// split two floats into packed bf16 hi/lo words
__device__ __forceinline__ void bsplit2(float x0, float x1, uint32_t& h, uint32_t& l) {
    __nv_bfloat16 h0 = __float2bfloat16(x0);
    __nv_bfloat16 h1 = __float2bfloat16(x1);
    __nv_bfloat16 l0 = __float2bfloat16(x0 - __bfloat162float(h0));
    __nv_bfloat16 l1 = __float2bfloat16(x1 - __bfloat162float(h1));
    h = pk(h0, h1);
    l = pk(l0, l1);
}
// D(16x8) += A(16x16,row) * B(16x8,col), bf16 in, f32 accum
__device__ __forceinline__ void mma_bf16(float* c, const uint32_t* a, const uint32_t* b) {
    asm volatile(
        "mma.sync.aligned.m16n8k16.row.col.f32.bf16.bf16.f32 "
        "{%0,%1,%2,%3}, {%4,%5,%6,%7}, {%8,%9}, {%0,%1,%2,%3};\n"
        : "+f"(c[0]), "+f"(c[1]), "+f"(c[2]), "+f"(c[3])
        : "r"(a[0]), "r"(a[1]), "r"(a[2]), "r"(a[3]),
          "r"(b[0]), "r"(b[1]));
}

__device__ __forceinline__ uint32_t smem_u32(const void* p) {
    uint32_t a;
    asm("{ .reg .u64 t; cvta.to.shared.u64 t, %1; cvt.u32.u64 %0, t; }"
        : "=r"(a) : "l"(p));
    return a;
}
#define CP16(dst_u32, src_ptr) \
    asm volatile("cp.async.cg.shared.global [%0], [%1], 16;" :: "r"(dst_u32), "l"(src_ptr))
#define CP_COMMIT()  asm volatile("cp.async.commit_group;")
#define CP_WAIT1()   asm volatile("cp.async.wait_group 1;")
#define CP_WAIT0()   asm volatile("cp.async.wait_group 0;")

// =================================================================
// One-shot weight split + transpose: [K][N] fp32 -> [N][K] bf16 hi/lo.
// =================================================================
#define N0_F4 (IN_DIM * HIDDEN / 4)
#define N1_F4 (N0_F4 + LAYERS * HIDDEN * 3 * HIDDEN / 4)
#define N2_F4 (N1_F4 + LAYERS * HIDDEN * HIDDEN / 4)
#define N3_F4 (N2_F4 + LAYERS * HIDDEN * FF_DIM / 4)
#define N4_F4 (N3_F4 + LAYERS * FF_DIM * HIDDEN / 4)
#define N5_F4 (N4_F4 + HIDDEN * OUT_DIM / 4)      // = W_TOTAL/4

__device__ __forceinline__ void wsplit_tr(const float* __restrict__ src,
                                          __nv_bfloat16* __restrict__ wh,
                                          __nv_bfloat16* __restrict__ wl,
                                          size_t j, int Ks, int Ns)
{
    const int k4s = Ks / 4;
    const size_t per = (size_t)Ks * Ns / 4;
    int layer = (int)(j / per);
    size_t r = j % per;
    int n = (int)(r / k4s);
    int k = (int)(r % k4s) * 4;
    const float* s = src + (size_t)layer * Ks * Ns;
    float v0 = s[(size_t)(k + 0) * Ns + n];
    float v1 = s[(size_t)(k + 1) * Ns + n];
    float v2 = s[(size_t)(k + 2) * Ns + n];
    float v3 = s[(size_t)(k + 3) * Ns + n];
    uint32_t h01, l01, h23, l23;
    bsplit2(v0, v1, h01, l01);
    bsplit2(v2, v3, h23, l23);
    size_t e = (size_t)layer * Ks * Ns + (size_t)n * Ks + k;
    uint2 hw = {h01, h23};
    uint2 lw = {l01, l23};
    *(uint2*)(wh + e) = hw;
    *(uint2*)(wl + e) = lw;
}

__global__ void __launch_bounds__(256)
split_weights(const float* __restrict__ s0, const float* __restrict__ s1,
              const float* __restrict__ s2, const float* __restrict__ s3,
              const float* __restrict__ s4, const float* __restrict__ s5,
              __nv_bfloat16* __restrict__ wh, __nv_bfloat16* __restrict__ wl)
{
    size_t i = (size_t)blockIdx.x * 256 + threadIdx.x;
    if (i >= (size_t)N5_F4) return;
    if      (i < N0_F4) wsplit_tr(s0, wh,             wl,             i,         IN_DIM, HIDDEN);
    else if (i < N1_F4) wsplit_tr(s1, wh + 4ul*N0_F4, wl + 4ul*N0_F4, i - N0_F4, HIDDEN, 3 * HIDDEN);
    else if (i < N2_F4) wsplit_tr(s2, wh + 4ul*N1_F4, wl + 4ul*N1_F4, i - N1_F4, HIDDEN, HIDDEN);
    else if (i < N3_F4) wsplit_tr(s3, wh + 4ul*N2_F4, wl + 4ul*N2_F4, i - N2_F4, HIDDEN, FF_DIM);
    else if (i < N4_F4) wsplit_tr(s4, wh + 4ul*N3_F4, wl + 4ul*N3_F4, i - N3_F4, FF_DIM, HIDDEN);
    else                wsplit_tr(s5, wh + 4ul*N4_F4, wl + 4ul*N4_F4, i - N4_F4, HIDDEN, OUT_DIM);
}

// =================================================================
// Elementwise bf16 hi/lo split (used only for x)
// =================================================================
__global__ void __launch_bounds__(256)
split_kernel(const float* __restrict__ src, __nv_bfloat16* __restrict__ hi,
             __nv_bfloat16* __restrict__ lo, int n4)
{
    int i = blockIdx.x * blockDim.x + threadIdx.x;
    if (i < n4) {
        float4 v = ((const float4*)src)[i];
        uint32_t h01, l01, h23, l23;
        bsplit2(v.x, v.y, h01, l01);
        bsplit2(v.z, v.w, h23, l23);
        uint2 hw = {h01, h23};
        uint2 lw = {l01, l23};
        ((uint2*)hi)[i] = hw;
        ((uint2*)lo)[i] = lw;
    }
}

// =================================================================
// Tensor-core GEMM: bf16 2-split (3 passes of m16n8k16), f32 accum.
// A [M][K] bf16 hi/lo; B (weights) [N][K] bf16 hi/lo (transposed).
// EPI: 0 = bias, 1 = bias+relu, 2 = bias then *32 + posenc
// SOUT: 0 = C fp32; 1 = Ch/Cl bf16 split; 2 = both
// smem per stage: 4 comps x 128 rows x 12 words (8 data + 4 pad).
// 3-stage cp.async, single barrier per tile. 2 CTAs/SM.
// =================================================================
#define RSW   12                                  // words per row
#define CMP_W (128 * RSW)                         // 1536 words per component
#define STG_W (4 * CMP_W)                         // 6144 words per stage
#define GEMM_SMEM (3 * STG_W * 4)                 // 73728 B

template<int EPI, int SOUT>
__global__ void __launch_bounds__(256, 2)
gemm_tc(const __nv_bfloat16* __restrict__ Ah, const __nv_bfloat16* __restrict__ Al,
        const __nv_bfloat16* __restrict__ Bh, const __nv_bfloat16* __restrict__ Bl,
        const float* __restrict__ bias, float* __restrict__ C,
        __nv_bfloat16* __restrict__ Ch, __nv_bfloat16* __restrict__ Cl,
        int M, int N, int K)
{
    extern __shared__ __align__(16) uint32_t wsm[];
    const uint32_t sbase = smem_u32(wsm);

    const int tid = threadIdx.x;
    const int cb = blockIdx.x * 128;
    const int rb = blockIdx.y * 128;

    // cp.async addressing: row = tid>>1, 16B half = tid&1 (8 bf16)
    const int arow = tid >> 1;
    const int ahalf = (tid & 1);

    const __nv_bfloat16* gAh = Ah + (size_t)(rb + arow) * K + ahalf * 8;
    const __nv_bfloat16* gAl = Al + (size_t)(rb + arow) * K + ahalf * 8;
    const __nv_bfloat16* gBh = Bh + (size_t)(cb + arow) * K + ahalf * 8;
    const __nv_bfloat16* gBl = Bl + (size_t)(cb + arow) * K + ahalf * 8;

    const int wid = tid >> 5, lane = tid & 31;
    const int grp = lane >> 2, t4 = lane & 3;
    const int m0 = (wid >> 2) * 64;
    const int n0 = (wid & 3) * 32;

    const uint32_t oW = (uint32_t)(arow * RSW + ahalf * 4) * 4;   // bytes

    auto issue_stage = [&](int s, int k0) {
        uint32_t sb = sbase + (uint32_t)(s * STG_W) * 4;
        CP16(sb + oW,                 gAh + k0);
        CP16(sb + oW + CMP_W * 4,     gAl + k0);
        CP16(sb + oW + 2 * CMP_W * 4, gBh + k0);
        CP16(sb + oW + 3 * CMP_W * 4, gBl + k0);
        CP_COMMIT();
    };

    float acc[4][4][4];
#pragma unroll
    for (int mt = 0; mt < 4; mt++)
#pragma unroll
        for (int nt = 0; nt < 4; nt++)
#pragma unroll
            for (int j = 0; j < 4; j++) acc[mt][nt][j] = 0.f;

    const int ntile = K / 16;
    issue_stage(0, 0);
    if (ntile > 1) issue_stage(1, 16);

    for (int i = 0; i < ntile; i++) {
        if (i + 1 < ntile) { CP_WAIT1(); } else { CP_WAIT0(); }
        __syncthreads();   // loads(i) visible AND compute(i-1) finished

        if (i + 2 < ntile) issue_stage((i + 2) % 3, (i + 2) * 16);

        const uint32_t* Ahs = wsm + (i % 3) * STG_W;
        const uint32_t* Als = Ahs + CMP_W;
        const uint32_t* Bhs = Als + CMP_W;
        const uint32_t* Bls = Bhs + CMP_W;

        uint32_t ah[4][4], al[4][4], bh[4][2], bl[4][2];
#pragma unroll
        for (int mt = 0; mt < 4; mt++) {
            int mr = m0 + mt * 16 + grp;
            ah[mt][0] = Ahs[mr * RSW + t4];
            ah[mt][1] = Ahs[(mr + 8) * RSW + t4];
            ah[mt][2] = Ahs[mr * RSW + 4 + t4];
            ah[mt][3] = Ahs[(mr + 8) * RSW + 4 + t4];
            al[mt][0] = Als[mr * RSW + t4];
            al[mt][1] = Als[(mr + 8) * RSW + t4];
            al[mt][2] = Als[mr * RSW + 4 + t4];
            al[mt][3] = Als[(mr + 8) * RSW + 4 + t4];
        }
#pragma unroll
        for (int nt = 0; nt < 4; nt++) {
            int nr = n0 + nt * 8 + grp;
            bh[nt][0] = Bhs[nr * RSW + t4];
            bh[nt][1] = Bhs[nr * RSW + 4 + t4];
            bl[nt][0] = Bls[nr * RSW + t4];
            bl[nt][1] = Bls[nr * RSW + 4 + t4];
        }
        // three passes, each 16 independent mmas
#pragma unroll
        for (int mt = 0; mt < 4; mt++)
#pragma unroll
            for (int nt = 0; nt < 4; nt++)
                mma_bf16(acc[mt][nt], ah[mt], bl[nt]);
#pragma unroll
        for (int mt = 0; mt < 4; mt++)
#pragma unroll
            for (int nt = 0; nt < 4; nt++)
                mma_bf16(acc[mt][nt], al[mt], bh[nt]);
#pragma unroll
        for (int mt = 0; mt < 4; mt++)
#pragma unroll
            for (int nt = 0; nt < 4; nt++)
                mma_bf16(acc[mt][nt], ah[mt], bh[nt]);
    }

    // ---- epilogue ----
#pragma unroll
    for (int mt = 0; mt < 4; mt++) {
#pragma unroll
        for (int nt = 0; nt < 4; nt++) {
            int col = cb + n0 + nt * 8 + 2 * t4;
            float b0 = bias[col], b1 = bias[col + 1];
#pragma unroll
            for (int half = 0; half < 2; half++) {
                int row = rb + m0 + mt * 16 + grp + half * 8;
                float c0 = acc[mt][nt][half * 2 + 0] + b0;
                float c1 = acc[mt][nt][half * 2 + 1] + b1;
                if (EPI == 1) { c0 = fmaxf(c0, 0.f); c1 = fmaxf(c1, 0.f); }
                if (EPI == 2) {
                    int srow = row & (SS - 1);
                    float f0 = expf(-9.210340371976184f * (float)(col & ~1) * (1.0f / 1024.0f));
                    float f1 = expf(-9.210340371976184f * (float)((col + 1) & ~1) * (1.0f / 1024.0f));
                    float a0 = (float)srow * f0, a1 = (float)srow * f1;
                    float p0 = (col & 1) ? cosf(a0) : sinf(a0);
                    float p1 = ((col + 1) & 1) ? cosf(a1) : sinf(a1);
                    c0 = c0 * 32.0f + p0;
                    c1 = c1 * 32.0f + p1;
                }
                size_t idx = (size_t)row * N + col;
                if (SOUT != 1) {
                    float2 o = {c0, c1};
                    *(float2*)(C + idx) = o;
                }
                if (SOUT >= 1) {
                    uint32_t hw, lw;
                    bsplit2(c0, c1, hw, lw);
                    *(uint32_t*)(Ch + idx) = hw;
                    *(uint32_t*)(Cl + idx) = lw;
                }
            }
        }
    }
}

// =================================================================
// Flash attention, 3xTF32 tensor cores, register-prefetched K/V.
// Writes ctx pre-split (bf16 hi/lo) for the out-projection GEMM.
// =================================================================
#define ASTR 68
#define ATTN_SMEM ((2 * 128 * ASTR + 2 * 64 * ASTR + 2 * 64 * ASTR + 2 * 128 * ASTR) * sizeof(float))  // 208896

__global__ void __launch_bounds__(256)
attn_tc(const float* __restrict__ qkv, __nv_bfloat16* __restrict__ ctxh,
        __nv_bfloat16* __restrict__ ctxl)
{
    extern __shared__ float sm[];
    float* Qh = sm;                  // [128][68]
    float* Ql = Qh + 128 * ASTR;
    float* Kh = Ql + 128 * ASTR;     // [64][68]
    float* Kl = Kh + 64 * ASTR;
    float* Vh = Kl + 64 * ASTR;      // [64][68]
    float* Vl = Vh + 64 * ASTR;
    float* Ph = Vl + 64 * ASTR;      // [128][68]
    float* Pl = Ph + 128 * ASTR;

    const int tid = threadIdx.x;
    const int q0 = blockIdx.x * 128;
    const int h  = blockIdx.y;
    const int b  = blockIdx.z;

    const int wid = tid >> 5, lane = tid & 31;
    const int grp = lane >> 2, t4 = lane & 3;
    const int mw = wid * 16;

    const int kv_r = tid >> 4;
    const int kv_c = (tid & 15) * 4;

    // ---- load Q tile (128 x 64), hi/lo split ----
    {
        const float* qbase = qkv + (size_t)(b * SS + q0) * 3 * HIDDEN + h * DH;
#pragma unroll
        for (int u = 0; u < 8; u++) {
            int idx = tid + u * 256;
            int r = idx >> 4, c = (idx & 15) * 4;
            float4 v = *(const float4*)(qbase + (size_t)r * 3 * HIDDEN + c);
            float4 hi, lo;
            split4(v, hi, lo);
            *(float4*)&Qh[r * ASTR + c] = hi;
            *(float4*)&Ql[r * ASTR + c] = lo;
        }
    }

    float out[8][4];
    float mi0 = -1e30f, mi1 = -1e30f, li0 = 0.f, li1 = 0.f;
#pragma unroll
    for (int nt = 0; nt < 8; nt++)
#pragma unroll
        for (int j = 0; j < 4; j++) out[nt][j] = 0.f;

    float4 kvr[4], vvr[4];
    {
        const float* kb = qkv + ((size_t)(b * SS) * 3 + 1) * HIDDEN + h * DH;
        const float* vb = kb + HIDDEN;
#pragma unroll
        for (int u = 0; u < 4; u++) {
            int r = kv_r + u * 16;
            kvr[u] = *(const float4*)(kb + (size_t)r * 3 * HIDDEN + kv_c);
            vvr[u] = *(const float4*)(vb + (size_t)r * 3 * HIDDEN + kv_c);
        }
    }

    for (int kt = 0; kt < SS / 64; kt++) {
#pragma unroll
        for (int u = 0; u < 4; u++) {
            int r = kv_r + u * 16;
            float4 hi, lo;
            split4(kvr[u], hi, lo);
            *(float4*)&Kh[r * ASTR + kv_c] = hi;
            *(float4*)&Kl[r * ASTR + kv_c] = lo;
            split4(vvr[u], hi, lo);
            *(float4*)&Vh[r * ASTR + kv_c] = hi;
            *(float4*)&Vl[r * ASTR + kv_c] = lo;
        }
        __syncthreads();

        if (kt + 1 < SS / 64) {
            const float* kb = qkv + ((size_t)(b * SS + (kt + 1) * 64) * 3 + 1) * HIDDEN + h * DH;
            const float* vb = kb + HIDDEN;
#pragma unroll
            for (int u = 0; u < 4; u++) {
                int r = kv_r + u * 16;
                kvr[u] = *(const float4*)(kb + (size_t)r * 3 * HIDDEN + kv_c);
                vvr[u] = *(const float4*)(vb + (size_t)r * 3 * HIDDEN + kv_c);
            }
        }

        // ---- S = Q @ K^T ----
        float sc[8][4];
#pragma unroll
        for (int nt = 0; nt < 8; nt++)
#pragma unroll
            for (int j = 0; j < 4; j++) sc[nt][j] = 0.f;

#pragma unroll
        for (int k8 = 0; k8 < 64; k8 += 8) {
            float ah[4], al[4];
            int mr = mw + grp;
            ah[0] = Qh[mr * ASTR + k8 + t4];
            ah[1] = Qh[(mr + 8) * ASTR + k8 + t4];
            ah[2] = Qh[mr * ASTR + k8 + t4 + 4];
            ah[3] = Qh[(mr + 8) * ASTR + k8 + t4 + 4];
            al[0] = Ql[mr * ASTR + k8 + t4];
            al[1] = Ql[(mr + 8) * ASTR + k8 + t4];
            al[2] = Ql[mr * ASTR + k8 + t4 + 4];
            al[3] = Ql[(mr + 8) * ASTR + k8 + t4 + 4];
#pragma unroll
            for (int nt = 0; nt < 8; nt++) {
                float bh[2], bl[2];
                int kr = nt * 8 + grp;
                bh[0] = Kh[kr * ASTR + k8 + t4];
                bh[1] = Kh[kr * ASTR + k8 + t4 + 4];
                bl[0] = Kl[kr * ASTR + k8 + t4];
                bl[1] = Kl[kr * ASTR + k8 + t4 + 4];
                mma3(sc[nt], ah, al, bh, bl);
            }
        }

        // ---- online softmax ----
        float rm0 = -1e30f, rm1 = -1e30f;
#pragma unroll
        for (int nt = 0; nt < 8; nt++) {
#pragma unroll
            for (int j = 0; j < 4; j++) sc[nt][j] *= 0.125f;
            rm0 = fmaxf(rm0, fmaxf(sc[nt][0], sc[nt][1]));
            rm1 = fmaxf(rm1, fmaxf(sc[nt][2], sc[nt][3]));
        }
#pragma unroll
        for (int off = 1; off < 4; off <<= 1) {
            rm0 = fmaxf(rm0, __shfl_xor_sync(0xffffffffu, rm0, off));
            rm1 = fmaxf(rm1, __shfl_xor_sync(0xffffffffu, rm1, off));
        }
        float mn0 = fmaxf(mi0, rm0), mn1 = fmaxf(mi1, rm1);
        float rs0 = 0.f, rs1 = 0.f;
#pragma unroll
        for (int nt = 0; nt < 8; nt++) {
            sc[nt][0] = __expf(sc[nt][0] - mn0);
            sc[nt][1] = __expf(sc[nt][1] - mn0);
            sc[nt][2] = __expf(sc[nt][2] - mn1);
            sc[nt][3] = __expf(sc[nt][3] - mn1);
            rs0 += sc[nt][0] + sc[nt][1];
            rs1 += sc[nt][2] + sc[nt][3];
        }
#pragma unroll
        for (int off = 1; off < 4; off <<= 1) {
            rs0 += __shfl_xor_sync(0xffffffffu, rs0, off);
            rs1 += __shfl_xor_sync(0xffffffffu, rs1, off);
        }
        float al0 = __expf(mi0 - mn0), al1 = __expf(mi1 - mn1);
        li0 = li0 * al0 + rs0;
        li1 = li1 * al1 + rs1;
        mi0 = mn0; mi1 = mn1;

        int pr0 = (mw + grp) * ASTR, pr1 = (mw + grp + 8) * ASTR;
#pragma unroll
        for (int nt = 0; nt < 8; nt++) {
            out[nt][0] *= al0; out[nt][1] *= al0;
            out[nt][2] *= al1; out[nt][3] *= al1;
            int pc = nt * 8 + 2 * t4;
            float h0 = tf32r(sc[nt][0]), h1 = tf32r(sc[nt][1]);
            float h2 = tf32r(sc[nt][2]), h3 = tf32r(sc[nt][3]);
            float2 ph0 = {h0, h1}, ph1 = {h2, h3};
            float2 pl0 = {tf32r(sc[nt][0] - h0), tf32r(sc[nt][1] - h1)};
            float2 pl1 = {tf32r(sc[nt][2] - h2), tf32r(sc[nt][3] - h3)};
            *(float2*)&Ph[pr0 + pc] = ph0;
            *(float2*)&Ph[pr1 + pc] = ph1;
            *(float2*)&Pl[pr0 + pc] = pl0;
            *(float2*)&Pl[pr1 + pc] = pl1;
        }
        __syncwarp();

        // ---- out += P @ V ----
#pragma unroll
        for (int k8 = 0; k8 < 64; k8 += 8) {
            float ah[4], al[4];
            int mr = mw + grp;
            ah[0] = Ph[mr * ASTR + k8 + t4];
            ah[1] = Ph[(mr + 8) * ASTR + k8 + t4];
            ah[2] = Ph[mr * ASTR + k8 + t4 + 4];
            ah[3] = Ph[(mr + 8) * ASTR + k8 + t4 + 4];
            al[0] = Pl[mr * ASTR + k8 + t4];
            al[1] = Pl[(mr + 8) * ASTR + k8 + t4];
            al[2] = Pl[mr * ASTR + k8 + t4 + 4];
            al[3] = Pl[(mr + 8) * ASTR + k8 + t4 + 4];
#pragma unroll
            for (int nt = 0; nt < 8; nt++) {
                float bh[2], bl[2];
                int nc = nt * 8 + grp;
                bh[0] = Vh[(k8 + t4) * ASTR + nc];
                bh[1] = Vh[(k8 + t4 + 4) * ASTR + nc];
                bl[0] = Vl[(k8 + t4) * ASTR + nc];
                bl[1] = Vl[(k8 + t4 + 4) * ASTR + nc];
                mma3(out[nt], ah, al, bh, bl);
            }
        }
        __syncthreads();
    }

    // ---- write ctx pre-split (bf16) ----
    float inv0 = 1.0f / li0, inv1 = 1.0f / li1;
    size_t row0 = (size_t)(b * SS + q0 + mw + grp) * HIDDEN + h * DH;
    size_t row1 = row0 + (size_t)8 * HIDDEN;
#pragma unroll
    for (int nt = 0; nt < 8; nt++) {
        int col = nt * 8 + 2 * t4;
        float v0 = out[nt][0] * inv0, v1 = out[nt][1] * inv0;
        float v2 = out[nt][2] * inv1, v3 = out[nt][3] * inv1;
        uint32_t hw0, lw0, hw1, lw1;
        bsplit2(v0, v1, hw0, lw0);
        bsplit2(v2, v3, hw1, lw1);
        *(uint32_t*)(ctxh + row0 + col) = hw0;
        *(uint32_t*)(ctxl + row0 + col) = lw0;
        *(uint32_t*)(ctxh + row1 + col) = hw1;
        *(uint32_t*)(ctxl + row1 + col) = lw1;
    }
}

// =================================================================
// LayerNorm: out = LN(x + res) * g + b; optional fp32 out and/or
// bf16 split outputs.
// =================================================================
__global__ void __launch_bounds__(256)
ln_kernel(const float* __restrict__ x, const float* __restrict__ res,
          const float* __restrict__ g, const float* __restrict__ beta,
          float* __restrict__ out, __nv_bfloat16* __restrict__ oh,
          __nv_bfloat16* __restrict__ ol)
{
    const int row = blockIdx.x;
    const int t = threadIdx.x;

    float4 v = ((const float4*)(x + (size_t)row * HIDDEN))[t];
    if (res) {
        float4 r = ((const float4*)(res + (size_t)row * HIDDEN))[t];
        v.x += r.x; v.y += r.y; v.z += r.z; v.w += r.w;
    }
    float s  = v.x + v.y + v.z + v.w;
    float sq = v.x * v.x + v.y * v.y + v.z * v.z + v.w * v.w;

#pragma unroll
    for (int off = 16; off > 0; off >>= 1) {
        s  += __shfl_xor_sync(0xffffffffu, s,  off);
        sq += __shfl_xor_sync(0xffffffffu, sq, off);
    }
    __shared__ float ss[8], ssq[8];
    __shared__ float smean, srstd;
    int warp = t >> 5, lane = t & 31;
    if (lane == 0) { ss[warp] = s; ssq[warp] = sq; }
    __syncthreads();
    if (t == 0) {
        float S = 0.f, Q = 0.f;
#pragma unroll
        for (int i = 0; i < 8; i++) { S += ss[i]; Q += ssq[i]; }
        float mean = S * (1.0f / HIDDEN);
        float var  = Q * (1.0f / HIDDEN) - mean * mean;
        smean = mean;
        srstd = rsqrtf(var + 1e-5f);
    }
    __syncthreads();
    float mean = smean, rstd = srstd;

    float4 gg = ((const float4*)g)[t];
    float4 bb = ((const float4*)beta)[t];
    float4 o;
    o.x = (v.x - mean) * rstd * gg.x + bb.x;
    o.y = (v.y - mean) * rstd * gg.y + bb.y;
    o.z = (v.z - mean) * rstd * gg.z + bb.z;
    o.w = (v.w - mean) * rstd * gg.w + bb.w;
    if (out) ((float4*)(out + (size_t)row * HIDDEN))[t] = o;
    if (oh) {
        uint32_t h01, l01, h23, l23;
        bsplit2(o.x, o.y, h01, l01);
        bsplit2(o.z, o.w, h23, l23);
        uint2 hw = {h01, h23};
        uint2 lw = {l01, l23};
        ((uint2*)(oh + (size_t)row * HIDDEN))[t] = hw;
        ((uint2*)(ol + (size_t)row * HIDDEN))[t] = lw;
    }
}

// =================================================================
// launch
// =================================================================
extern "C" void kernel_launch(void* const* d_in, const int* in_sizes, int n_in,
                              void* d_out, int out_size)
{
    const float* x     = (const float*)d_in[0];
    const float* in_W  = (const float*)d_in[1];
    const float* in_b  = (const float*)d_in[2];
    const float* qkv_W = (const float*)d_in[3];
    const float* qkv_b = (const float*)d_in[4];
    const float* out_W = (const float*)d_in[5];
    const float* out_b = (const float*)d_in[6];
    const float* ln1_g = (const float*)d_in[7];
    const float* ln1_b = (const float*)d_in[8];
    const float* ln2_g = (const float*)d_in[9];
    const float* ln2_b = (const float*)d_in[10];
    const float* ff1_W = (const float*)d_in[11];
    const float* ff1_b = (const float*)d_in[12];
    const float* ff2_W = (const float*)d_in[13];
    const float* ff2_b = (const float*)d_in[14];
    const float* fin_g = (const float*)d_in[15];
    const float* fin_b = (const float*)d_in[16];
    const float* op_W  = (const float*)d_in[17];
    const float* op_b  = (const float*)d_in[18];
    float* out = (float*)d_out;

    float *h, *qkv, *y;
    __nv_bfloat16 *wh, *wl, *ah, *al, *fh, *fl;
    cudaGetSymbolAddress((void**)&h,   g_h);
    cudaGetSymbolAddress((void**)&qkv, g_qkv);
    cudaGetSymbolAddress((void**)&y,   g_y);
    cudaGetSymbolAddress((void**)&wh,  g_wh);
    cudaGetSymbolAddress((void**)&wl,  g_wl);
    cudaGetSymbolAddress((void**)&ah,  g_ah);
    cudaGetSymbolAddress((void**)&al,  g_al);
    cudaGetSymbolAddress((void**)&fh,  g_fh);
    cudaGetSymbolAddress((void**)&fl,  g_fl);

    cudaFuncSetAttribute(attn_tc, cudaFuncAttributeMaxDynamicSharedMemorySize,
                         (int)ATTN_SMEM);
    cudaFuncSetAttribute((gemm_tc<0,0>), cudaFuncAttributeMaxDynamicSharedMemorySize, (int)GEMM_SMEM);
    cudaFuncSetAttribute((gemm_tc<1,1>), cudaFuncAttributeMaxDynamicSharedMemorySize, (int)GEMM_SMEM);
    cudaFuncSetAttribute((gemm_tc<2,2>), cudaFuncAttributeMaxDynamicSharedMemorySize, (int)GEMM_SMEM);

    const int M = M_ROWS;
    dim3 blk(256);

    // weight arena offsets (bf16 elements) — each matrix stored [N][K]
    const size_t ofs_in  = 0;
    const size_t ofs_qkv = ofs_in  + (size_t)IN_DIM * HIDDEN;
    const size_t ofs_out = ofs_qkv + (size_t)LAYERS * HIDDEN * 3 * HIDDEN;
    const size_t ofs_ff1 = ofs_out + (size_t)LAYERS * HIDDEN * HIDDEN;
    const size_t ofs_ff2 = ofs_ff1 + (size_t)LAYERS * HIDDEN * FF_DIM;
    const size_t ofs_op  = ofs_ff2 + (size_t)LAYERS * FF_DIM * HIDDEN;

    // L0: all weights split + transposed (one launch)
    split_weights<<<(N5_F4 + 255) / 256, blk>>>(in_W, qkv_W, out_W, ff1_W,
                                                ff2_W, op_W, wh, wl);
    // L1: x split into fh/fl
    {
        int n4 = M * IN_DIM / 4;
        split_kernel<<<(n4 + 255) / 256, blk>>>(x, fh, fl, n4);
    }
    // L2: input projection + posenc; writes h fp32 AND h split
    gemm_tc<2, 2><<<dim3(HIDDEN / 128, M / 128), blk, GEMM_SMEM>>>(
        fh, fl, wh + ofs_in, wl + ofs_in, in_b, h, ah, al, M, HIDDEN, IN_DIM);

    for (int l = 0; l < LAYERS; l++) {
        const float* qb  = qkv_b + (size_t)l * 3 * HIDDEN;
        const float* ob  = out_b + (size_t)l * HIDDEN;
        const float* f1b = ff1_b + (size_t)l * FF_DIM;
        const float* f2b = ff2_b + (size_t)l * HIDDEN;
        size_t wq  = ofs_qkv + (size_t)l * HIDDEN * 3 * HIDDEN;
        size_t wo  = ofs_out + (size_t)l * HIDDEN * HIDDEN;
        size_t wf1 = ofs_ff1 + (size_t)l * HIDDEN * FF_DIM;
        size_t wf2 = ofs_ff2 + (size_t)l * FF_DIM * HIDDEN;

        // qkv projection (reads h split)
        gemm_tc<0, 0><<<dim3(3 * HIDDEN / 128, M / 128), blk, GEMM_SMEM>>>(
            ah, al, wh + wq, wl + wq, qb, qkv, nullptr, nullptr, M, 3 * HIDDEN, HIDDEN);
        // attention: writes ctx split into ah/al
        attn_tc<<<dim3(SS / 128, HEADS, BB), blk, ATTN_SMEM>>>(qkv, ah, al);
        // out projection (reads ctx split)
        gemm_tc<0, 0><<<dim3(HIDDEN / 128, M / 128), blk, GEMM_SMEM>>>(
            ah, al, wh + wo, wl + wo, ob, y, nullptr, nullptr, M, HIDDEN, HIDDEN);
        // LN1: h = LN(h + y); writes fp32 h + h split
        ln_kernel<<<M, blk>>>(h, y, ln1_g + l * HIDDEN, ln1_b + l * HIDDEN, h, ah, al);
        // FF1 (reads h split), relu, writes ff split
        gemm_tc<1, 1><<<dim3(FF_DIM / 128, M / 128), blk, GEMM_SMEM>>>(
            ah, al, wh + wf1, wl + wf1, f1b, nullptr, fh, fl, M, FF_DIM, HIDDEN);
        // FF2 (reads ff split)
        gemm_tc<0, 0><<<dim3(HIDDEN / 128, M / 128), blk, GEMM_SMEM>>>(
            fh, fl, wh + wf2, wl + wf2, f2b, y, nullptr, nullptr, M, HIDDEN, FF_DIM);
        // LN2: h = LN(h + y); writes fp32 h + h split
        ln_kernel<<<M, blk>>>(h, y, ln2_g + l * HIDDEN, ln2_b + l * HIDDEN, h, ah, al);
    }

    // final LN (split only) then output projection
    ln_kernel<<<M, blk>>>(h, nullptr, fin_g, fin_b, nullptr, ah, al);
    gemm_tc<0, 0><<<dim3(OUT_DIM / 128, M / 128), blk, GEMM_SMEM>>>(
        ah, al, wh + ofs_op, wl + ofs_op, op_b, out, nullptr, nullptr, M, OUT_DIM, HIDDEN);
}